// round 13
// baseline (speedup 1.0000x reference)
#include <cuda_runtime.h>

#ifndef PI_F
#define PI_F 3.14159265358979323846f
#endif

// v5: R2's proven max-bandwidth shape (U=4 front-batched float4 loads,
// regs~28, full occupancy) + uniform cache policies (no per-load select,
// which cost R6 ~0.4TB/s of issue headroom):
//   - all input loads:  L2::evict_first (pure stream, touched once)
//   - all output stores: L2::evict_last (output stays L2-resident across
//     graph replays; R8 measured write traffic ~0)

__device__ __forceinline__ float4 ldg_nc_hint(const float4* p, unsigned long long pol) {
    float4 v;
    asm("ld.global.nc.L2::cache_hint.v4.f32 {%0,%1,%2,%3}, [%4], %5;"
        : "=f"(v.x), "=f"(v.y), "=f"(v.z), "=f"(v.w) : "l"(p), "l"(pol));
    return v;
}

__device__ __forceinline__ void stg_hint2(float2* p, float2 v, unsigned long long pol) {
    asm volatile("st.global.L2::cache_hint.v2.f32 [%0], {%1,%2}, %3;"
                 :: "l"(p), "f"(v.x), "f"(v.y), "l"(pol) : "memory");
}

__global__ void __launch_bounds__(256) helm_kernel(
    const float4* __restrict__ in4,   // [n4] float4 = 2 rows each
    const float* __restrict__ a,      // [1]
    float2* __restrict__ out2,        // [n4]
    int n4)
{
    const int T = 256;
    const int U = 4;
    int base = blockIdx.x * (T * U) + threadIdx.x;

    unsigned long long pol_first, pol_last;
    asm("createpolicy.fractional.L2::evict_first.b64 %0, 1.0;" : "=l"(pol_first));
    asm("createpolicy.fractional.L2::evict_last.b64 %0, 1.0;"  : "=l"(pol_last));

    float av = __ldg(a);
    float coef = av * av - 2.0f * PI_F * PI_F;

    if (base + 3 * T < n4) {
        float4 v[U];
        #pragma unroll
        for (int k = 0; k < U; k++)
            v[k] = ldg_nc_hint(&in4[base + k * T], pol_first);

        float2 r[U];
        #pragma unroll
        for (int k = 0; k < U; k++) {
            r[k].x = coef * __sinf(PI_F * v[k].x) * __sinf(PI_F * v[k].y);
            r[k].y = coef * __sinf(PI_F * v[k].z) * __sinf(PI_F * v[k].w);
        }

        #pragma unroll
        for (int k = 0; k < U; k++)
            stg_hint2(&out2[base + k * T], r[k], pol_last);
    } else {
        #pragma unroll
        for (int k = 0; k < U; k++) {
            int i = base + k * T;
            if (i < n4) {
                float4 v = ldg_nc_hint(&in4[i], pol_first);
                float2 r = make_float2(coef * __sinf(PI_F * v.x) * __sinf(PI_F * v.y),
                                       coef * __sinf(PI_F * v.z) * __sinf(PI_F * v.w));
                stg_hint2(&out2[i], r, pol_last);
            }
        }
    }
}

extern "C" void kernel_launch(void* const* d_in, const int* in_sizes, int n_in,
                              void* d_out, int out_size) {
    const float* input = (const float*)d_in[0];   // [N, 2]
    const float* a     = (const float*)d_in[1];   // [1]
    float* out         = (float*)d_out;           // [N, 1]

    int n_rows = in_sizes[0] / 2;   // N
    int n4 = n_rows / 2;            // float4 count (N even)

    int threads = 256;
    int per_block = threads * 4;
    int blocks = (n4 + per_block - 1) / per_block;
    helm_kernel<<<blocks, threads>>>(
        (const float4*)input, a, (float2*)out, n4);
}